// round 1
// baseline (speedup 1.0000x reference)
#include <cuda_runtime.h>

// OWNNorm: per-group ZCA whitening of weight [4096, 16384], G=16 groups of c=256 rows.
// W = S^{-1/2} Zc with S = Zc Zc^T, computed via Newton-Schulz inverse sqrt (pure GEMM).

#define NROW 4096
#define D    16384
#define G    16
#define C    256
#define SPLITK 8
#define KC   (D / SPLITK)      // 2048
#define NS_ITERS 8
#define GV   (G * C * C)       // 1048576 floats per NS slot

__device__ float g_mean[NROW];
__device__ float g_Spart[(size_t)SPLITK * GV];   // split-K partials (deterministic, no atomics)
__device__ float g_S[GV];
__device__ float g_ns[(size_t)5 * GV];           // slots: Y, Z, Y', Z', T
__device__ float g_norm[G];
__device__ float g_corr[NROW];

// ---------------------------------------------------------------- row means
__global__ void k_mean(const float* __restrict__ W) {
    int row = blockIdx.x;
    const float4* p = (const float4*)(W + (size_t)row * D);
    float s = 0.f;
    for (int k = threadIdx.x; k < D / 4; k += 256) {
        float4 v = p[k];
        s += (v.x + v.y) + (v.z + v.w);
    }
    __shared__ float red[256];
    red[threadIdx.x] = s;
    __syncthreads();
    for (int st = 128; st > 0; st >>= 1) {
        if (threadIdx.x < st) red[threadIdx.x] += red[threadIdx.x + st];
        __syncthreads();
    }
    if (threadIdx.x == 0) g_mean[row] = red[0] * (1.f / (float)D);
}

// ------------------------------------------- SYRK partials: S_part = A A^T (NT GEMM)
// 128x128 tile, 8x8 microtile, BK=8, 256 threads. grid (2,2,G*SPLITK).
__global__ __launch_bounds__(256) void k_syrk(const float* __restrict__ W) {
    int g  = blockIdx.z >> 3;
    int ks = blockIdx.z & 7;
    const float* A = W + (size_t)g * C * D;

    int tid  = threadIdx.x;
    int lrow = tid >> 1;            // 0..127
    int lk4  = (tid & 1) * 4;       // 0 or 4
    const float* Ap = A + (size_t)(blockIdx.x * 128 + lrow) * D + ks * KC + lk4;
    const float* Bp = A + (size_t)(blockIdx.y * 128 + lrow) * D + ks * KC + lk4;

    __shared__ float As[8][132];
    __shared__ float Bs[8][132];

    int ty = tid >> 4, tx = tid & 15;
    float acc[8][8] = {};

    for (int kt = 0; kt < KC; kt += 8) {
        float4 av = *(const float4*)(Ap + kt);
        float4 bv = *(const float4*)(Bp + kt);
        __syncthreads();
        As[lk4 + 0][lrow] = av.x; As[lk4 + 1][lrow] = av.y;
        As[lk4 + 2][lrow] = av.z; As[lk4 + 3][lrow] = av.w;
        Bs[lk4 + 0][lrow] = bv.x; Bs[lk4 + 1][lrow] = bv.y;
        Bs[lk4 + 2][lrow] = bv.z; Bs[lk4 + 3][lrow] = bv.w;
        __syncthreads();
#pragma unroll
        for (int kk = 0; kk < 8; kk++) {
            float a[8], b[8];
            *(float4*)&a[0] = *(const float4*)&As[kk][ty * 8];
            *(float4*)&a[4] = *(const float4*)&As[kk][ty * 8 + 4];
            *(float4*)&b[0] = *(const float4*)&Bs[kk][tx * 8];
            *(float4*)&b[4] = *(const float4*)&Bs[kk][tx * 8 + 4];
#pragma unroll
            for (int i = 0; i < 8; i++)
#pragma unroll
                for (int j = 0; j < 8; j++) acc[i][j] = fmaf(a[i], b[j], acc[i][j]);
        }
    }

    float* Cp = g_Spart + ((size_t)ks * G + g) * (C * C);
#pragma unroll
    for (int i = 0; i < 8; i++) {
        int r = blockIdx.x * 128 + ty * 8 + i;
        float* o = Cp + (size_t)r * C + blockIdx.y * 128 + tx * 8;
        *(float4*)(o)     = make_float4(acc[i][0], acc[i][1], acc[i][2], acc[i][3]);
        *(float4*)(o + 4) = make_float4(acc[i][4], acc[i][5], acc[i][6], acc[i][7]);
    }
}

// --------------------------- reduce split-K partials, subtract d*mean*mean^T
__global__ void k_reduceS() {
    int idx = blockIdx.x * 256 + threadIdx.x;   // < GV
    int g  = idx >> 16;
    int ij = idx & 65535;
    int i = ij >> 8, j = ij & 255;
    float s = 0.f;
#pragma unroll
    for (int p = 0; p < SPLITK; p++) s += g_Spart[((size_t)p * G + g) * (C * C) + ij];
    s -= (float)D * g_mean[g * C + i] * g_mean[g * C + j];
    g_S[idx] = s;
}

// --------------------------------------- inf-norm per group (>= lambda_max)
__global__ void k_infnorm() {
    int g = blockIdx.x, i = threadIdx.x;
    const float* row = g_S + (size_t)g * (C * C) + (size_t)i * C;
    float s = 0.f;
    for (int j = 0; j < C; j++) s += fabsf(row[j]);
    __shared__ float red[256];
    red[i] = s;
    __syncthreads();
    for (int st = 128; st > 0; st >>= 1) {
        if (i < st) red[i] = fmaxf(red[i], red[i + st]);
        __syncthreads();
    }
    if (i == 0) g_norm[g] = red[0];
}

// ------------------------------------------------ Y0 = S/s, Z0 = I
__global__ void k_initYZ(int ys, int zs) {
    int idx = blockIdx.x * 256 + threadIdx.x;
    int g  = idx >> 16;
    int ij = idx & 65535;
    float inv = 1.f / g_norm[g];
    g_ns[(size_t)ys * GV + idx] = g_S[idx] * inv;
    g_ns[(size_t)zs * GV + idx] = ((ij >> 8) == (ij & 255)) ? 1.f : 0.f;
}

// ----------------- batched 256x256x256 GEMM over G groups (NS iterations)
// mode 0: C = A @ B ; mode 1: C = 1.5*I - 0.5*(A @ B)
__global__ __launch_bounds__(256) void k_gemm256(int as_, int bs_, int cs_, int mode) {
    const float* A = g_ns + (size_t)as_ * GV + (size_t)blockIdx.z * (C * C);
    const float* B = g_ns + (size_t)bs_ * GV + (size_t)blockIdx.z * (C * C);
    float*       Cm = g_ns + (size_t)cs_ * GV + (size_t)blockIdx.z * (C * C);

    __shared__ float As[16][68];
    __shared__ float Bs[16][68];

    int tid = threadIdx.x;
    int arow  = tid >> 2;            // 0..63
    int ak4   = (tid & 3) * 4;       // 0,4,8,12
    int brow  = tid >> 4;            // 0..15
    int bcol4 = (tid & 15) * 4;      // 0..60
    int ty = tid >> 4, tx = tid & 15;

    float acc[4][4] = {};
    const float* Ap = A + (size_t)(blockIdx.x * 64 + arow) * C + ak4;
    const float* Bp = B + blockIdx.y * 64 + bcol4;

    for (int k0 = 0; k0 < C; k0 += 16) {
        float4 av = *(const float4*)(Ap + k0);
        float4 bv = *(const float4*)(Bp + (size_t)(k0 + brow) * C);
        __syncthreads();
        As[ak4 + 0][arow] = av.x; As[ak4 + 1][arow] = av.y;
        As[ak4 + 2][arow] = av.z; As[ak4 + 3][arow] = av.w;
        *(float4*)&Bs[brow][bcol4] = bv;
        __syncthreads();
#pragma unroll
        for (int kk = 0; kk < 16; kk++) {
            float a[4], b[4];
            *(float4*)a = *(const float4*)&As[kk][ty * 4];
            *(float4*)b = *(const float4*)&Bs[kk][tx * 4];
#pragma unroll
            for (int i = 0; i < 4; i++)
#pragma unroll
                for (int j = 0; j < 4; j++) acc[i][j] = fmaf(a[i], b[j], acc[i][j]);
        }
    }

#pragma unroll
    for (int i = 0; i < 4; i++) {
        int r = blockIdx.x * 64 + ty * 4 + i;
#pragma unroll
        for (int j = 0; j < 4; j++) {
            int cc = blockIdx.y * 64 + tx * 4 + j;
            float v = acc[i][j];
            if (mode == 1) v = ((r == cc) ? 1.5f : 0.f) - 0.5f * v;
            Cm[(size_t)r * C + cc] = v;
        }
    }
}

// ---------------------------- corr = (Z_f/sqrt(s)) @ mean   (per group row)
__global__ void k_corr(int zs) {
    int g = blockIdx.x, i = threadIdx.x;
    const float* Zr = g_ns + (size_t)zs * GV + (size_t)g * (C * C) + (size_t)i * C;
    const float* m  = g_mean + g * C;
    float s = 0.f;
    for (int j = 0; j < C; j++) s = fmaf(Zr[j], m[j], s);
    g_corr[g * C + i] = s * rsqrtf(g_norm[g]);
}

// ---------- final: out = scale*(Z_f @ Wgroup) - corr[row], N=16384 wide GEMM
// 128x128 tile, 8x8 microtile, BK=8. grid (2, 128, G).
__global__ __launch_bounds__(256) void k_final(const float* __restrict__ W,
                                               float* __restrict__ out, int zs) {
    int g = blockIdx.z;
    const float* A = g_ns + (size_t)zs * GV + (size_t)g * (C * C);  // 256x256
    const float* B = W + (size_t)g * C * D;                          // 256xD

    __shared__ float As[8][132];
    __shared__ float Bs[8][132];

    int tid = threadIdx.x;
    int arow  = tid >> 1;           // 0..127
    int ak4   = (tid & 1) * 4;      // 0 or 4
    int brow  = tid >> 5;           // 0..7
    int bcol4 = (tid & 31) * 4;     // 0..124
    int ty = tid >> 4, tx = tid & 15;

    float acc[8][8] = {};
    const float* Ap = A + (size_t)(blockIdx.x * 128 + arow) * C + ak4;
    const float* Bp = B + (size_t)brow * D + blockIdx.y * 128 + bcol4;

    for (int k0 = 0; k0 < C; k0 += 8) {
        float4 av = *(const float4*)(Ap + k0);
        float4 bv = *(const float4*)(Bp + (size_t)k0 * D);
        __syncthreads();
        As[ak4 + 0][arow] = av.x; As[ak4 + 1][arow] = av.y;
        As[ak4 + 2][arow] = av.z; As[ak4 + 3][arow] = av.w;
        *(float4*)&Bs[brow][bcol4] = bv;
        __syncthreads();
#pragma unroll
        for (int kk = 0; kk < 8; kk++) {
            float a[8], b[8];
            *(float4*)&a[0] = *(const float4*)&As[kk][ty * 8];
            *(float4*)&a[4] = *(const float4*)&As[kk][ty * 8 + 4];
            *(float4*)&b[0] = *(const float4*)&Bs[kk][tx * 8];
            *(float4*)&b[4] = *(const float4*)&Bs[kk][tx * 8 + 4];
#pragma unroll
            for (int i = 0; i < 8; i++)
#pragma unroll
                for (int j = 0; j < 8; j++) acc[i][j] = fmaf(a[i], b[j], acc[i][j]);
        }
    }

    float scale = rsqrtf(g_norm[g]);
#pragma unroll
    for (int i = 0; i < 8; i++) {
        int r = blockIdx.x * 128 + ty * 8 + i;
        float cr = g_corr[g * C + r];
        float* o = out + ((size_t)(g * C + r)) * D + blockIdx.y * 128 + tx * 8;
        *(float4*)(o)     = make_float4(fmaf(scale, acc[i][0], -cr), fmaf(scale, acc[i][1], -cr),
                                        fmaf(scale, acc[i][2], -cr), fmaf(scale, acc[i][3], -cr));
        *(float4*)(o + 4) = make_float4(fmaf(scale, acc[i][4], -cr), fmaf(scale, acc[i][5], -cr),
                                        fmaf(scale, acc[i][6], -cr), fmaf(scale, acc[i][7], -cr));
    }
}

extern "C" void kernel_launch(void* const* d_in, const int* in_sizes, int n_in,
                              void* d_out, int out_size) {
    const float* W = (const float*)d_in[0];
    float* out = (float*)d_out;

    k_mean<<<NROW, 256>>>(W);
    k_syrk<<<dim3(2, 2, G * SPLITK), 256>>>(W);
    k_reduceS<<<GV / 256, 256>>>();
    k_infnorm<<<G, 256>>>();

    int y = 0, z = 1, ya = 2, za = 3, T = 4;
    k_initYZ<<<GV / 256, 256>>>(y, z);

    for (int it = 0; it < NS_ITERS; it++) {
        // T = 1.5 I - 0.5 (Z @ Y)
        k_gemm256<<<dim3(4, 4, G), 256>>>(z, y, T, 1);
        // Y' = Y @ T ; Z' = T @ Z
        k_gemm256<<<dim3(4, 4, G), 256>>>(y, T, ya, 0);
        k_gemm256<<<dim3(4, 4, G), 256>>>(T, z, za, 0);
        int t1 = y; y = ya; ya = t1;
        t1 = z; z = za; za = t1;
    }

    k_corr<<<G, 256>>>(z);
    k_final<<<dim3(2, 128, G), 256>>>(W, out, z);
}

// round 5
// speedup vs baseline: 2.1564x; 2.1564x over previous
#include <cuda_runtime.h>
#include <cuda_bf16.h>
#include <cstdint>

// OWNNorm: per-group ZCA whitening of weight [4096, 16384], G=16 groups of c=256 rows.
// W = S^{-1/2} Zc via Newton-Schulz. Big GEMMs: mma.sync bf16, 2-way split, on-the-fly convert.

#define NROW 4096
#define D    16384
#define G    16
#define C    256
#define SK   4
#define KCTA (D / SK)          // 4096
#define NS_ITERS 6
#define GV   (G * C * C)

#define BK   16
#define LROW 48                // A-side smem row stride (16 bf16 + pad)
#define MATA (128 * LROW)      // 6144
#define STAGE_S (4 * MATA)     // 24576: Ahi,Alo,Bhi,Blo (SYRK)
#define BROW 272               // final B smem row stride (128 bf16 + 16B pad)
#define FB_HI (2 * MATA)       // 12288
#define FB_LO (FB_HI + 16 * BROW)   // 16640
#define STAGE_F (FB_LO + 16 * BROW) // 20992

// ------------------------------------------------------------------ globals (~45 MiB)
__device__ float g_mean[NROW];
__device__ float g_Spart[(size_t)SK * GV];
__device__ float g_S[GV];
__device__ float g_ns[(size_t)5 * GV];
__device__ float g_norm[G];
__device__ float g_corr[NROW];
__device__ __nv_bfloat16 g_Zhi[GV];
__device__ __nv_bfloat16 g_Zlo[GV];

// ------------------------------------------------------------- PTX helpers
__device__ __forceinline__ uint32_t smem_u32(const void* p) {
    uint32_t a;
    asm("{ .reg .u64 t; cvta.to.shared.u64 t, %1; cvt.u32.u64 %0, t; }" : "=r"(a) : "l"(p));
    return a;
}
#define CP16(s, g) asm volatile("cp.async.cg.shared.global [%0], [%1], 16;" \
    :: "r"(s), "l"(__cvta_generic_to_global((const void*)(g))) : "memory")
#define CP_COMMIT() asm volatile("cp.async.commit_group;" ::: "memory")
#define CP_WAIT1()  asm volatile("cp.async.wait_group 1;" ::: "memory")
#define CP_WAIT0()  asm volatile("cp.async.wait_group 0;" ::: "memory")

__device__ __forceinline__ void ldsm4(uint32_t* r, uint32_t addr) {
    asm volatile("ldmatrix.sync.aligned.m8n8.x4.shared.b16 {%0,%1,%2,%3}, [%4];"
        : "=r"(r[0]), "=r"(r[1]), "=r"(r[2]), "=r"(r[3]) : "r"(addr));
}
__device__ __forceinline__ void ldsm4t(uint32_t* r, uint32_t addr) {
    asm volatile("ldmatrix.sync.aligned.m8n8.x4.trans.shared.b16 {%0,%1,%2,%3}, [%4];"
        : "=r"(r[0]), "=r"(r[1]), "=r"(r[2]), "=r"(r[3]) : "r"(addr));
}
__device__ __forceinline__ void mma16816(float* d, const uint32_t* a, const uint32_t* b) {
    asm volatile(
        "mma.sync.aligned.m16n8k16.row.col.f32.bf16.bf16.f32 "
        "{%0,%1,%2,%3}, {%4,%5,%6,%7}, {%8,%9}, {%0,%1,%2,%3};"
        : "+f"(d[0]), "+f"(d[1]), "+f"(d[2]), "+f"(d[3])
        : "r"(a[0]), "r"(a[1]), "r"(a[2]), "r"(a[3]), "r"(b[0]), "r"(b[1]));
}
// split 8 f32 (two float4) -> 8 bf16 hi (uint4) + 8 bf16 lo (uint4)
__device__ __forceinline__ void split8(float4 u, float4 v, uint4& h, uint4& l) {
    float uu[8] = {u.x, u.y, u.z, u.w, v.x, v.y, v.z, v.w};
    uint32_t hh[4], ll[4];
#pragma unroll
    for (int k = 0; k < 4; k++) {
        __nv_bfloat16 ha = __float2bfloat16_rn(uu[2*k]),   hb = __float2bfloat16_rn(uu[2*k+1]);
        __nv_bfloat16 la = __float2bfloat16_rn(uu[2*k]   - __bfloat162float(ha));
        __nv_bfloat16 lb = __float2bfloat16_rn(uu[2*k+1] - __bfloat162float(hb));
        hh[k] = (uint32_t)__bfloat16_as_ushort(ha) | ((uint32_t)__bfloat16_as_ushort(hb) << 16);
        ll[k] = (uint32_t)__bfloat16_as_ushort(la) | ((uint32_t)__bfloat16_as_ushort(lb) << 16);
    }
    h = make_uint4(hh[0], hh[1], hh[2], hh[3]);
    l = make_uint4(ll[0], ll[1], ll[2], ll[3]);
}

// ---------------------------------------------------------------- row means
__global__ void k_mean(const float* __restrict__ W) {
    int row = blockIdx.x;
    const float4* p = (const float4*)(W + (size_t)row * D);
    float s = 0.f;
    for (int k = threadIdx.x; k < D / 4; k += 256) {
        float4 v = p[k];
        s += (v.x + v.y) + (v.z + v.w);
    }
    __shared__ float red[256];
    red[threadIdx.x] = s;
    __syncthreads();
    for (int st = 128; st > 0; st >>= 1) {
        if (threadIdx.x < st) red[threadIdx.x] += red[threadIdx.x + st];
        __syncthreads();
    }
    if (threadIdx.x == 0) g_mean[row] = red[0] * (1.f / (float)D);
}

// --------------------------------------------------------- mma.sync SYRK (on-the-fly convert)
// grid (3, 1, G*SK): tile id 0->(0,0) 1->(0,1) 2->(1,1); (1,0) by symmetry.
__global__ void __launch_bounds__(256) k_syrk_mma(const float* __restrict__ W) {
    __shared__ char smbuf[2 * STAGE_S];    // 49152
    uint32_t sb = smem_u32(smbuf);
    int tid = threadIdx.x, lane = tid & 31, wid = tid >> 5;
    int warp_m = wid >> 2, warp_n = wid & 3;
    int txy = blockIdx.x;
    int bx = (txy == 2), by = (txy > 0);
    int g = blockIdx.z >> 2, ks = blockIdx.z & 3;

    int lrow = tid >> 1, half = tid & 1;
    const float* pA = W + (size_t)(g * C + bx * 128 + lrow) * D + (size_t)ks * KCTA + half * 8;
    const float* pB = W + (size_t)(g * C + by * 128 + lrow) * D + (size_t)ks * KCTA + half * 8;
    uint32_t so = (uint32_t)(lrow * LROW + half * 16);

    uint32_t a_off = (warp_m * 64 + (lane & 15)) * LROW + (lane >> 4) * 16;
    uint32_t b_off = (warp_n * 32 + ((lane >> 4) << 3) + (lane & 7)) * LROW + ((lane >> 3) & 1) * 16;

    float acc[4][4][4] = {};

    float4 a0 = *(const float4*)pA, a1 = *(const float4*)(pA + 4);
    float4 b0 = *(const float4*)pB, b1 = *(const float4*)(pB + 4);

    const int NST = KCTA / BK;   // 256
    for (int s = 0; s < NST; s++) {
        uint32_t st = sb + (s & 1) * STAGE_S;
        char* stp = smbuf + (s & 1) * STAGE_S;
        uint4 ah, al, bh_, bl_;
        split8(a0, a1, ah, al);
        split8(b0, b1, bh_, bl_);
        *(uint4*)(stp + so)            = ah;
        *(uint4*)(stp + MATA + so)     = al;
        *(uint4*)(stp + 2*MATA + so)   = bh_;
        *(uint4*)(stp + 3*MATA + so)   = bl_;
        __syncthreads();
        if (s + 1 < NST) {
            const float* qA = pA + (size_t)(s + 1) * BK;
            const float* qB = pB + (size_t)(s + 1) * BK;
            a0 = *(const float4*)qA; a1 = *(const float4*)(qA + 4);
            b0 = *(const float4*)qB; b1 = *(const float4*)(qB + 4);
        }
        uint32_t bh[2][4], bl[2][4];
#pragma unroll
        for (int p = 0; p < 2; p++) {
            ldsm4(bh[p], st + 2*MATA + b_off + p * 16 * LROW);
            ldsm4(bl[p], st + 3*MATA + b_off + p * 16 * LROW);
        }
#pragma unroll
        for (int mt = 0; mt < 4; mt++) {
            uint32_t am[4], av[4];
            ldsm4(am, st + a_off + mt * 16 * LROW);
            ldsm4(av, st + MATA + a_off + mt * 16 * LROW);
#pragma unroll
            for (int p = 0; p < 2; p++)
#pragma unroll
                for (int q = 0; q < 2; q++) {
                    mma16816(acc[mt][p*2+q], am, &bh[p][q*2]);
                    mma16816(acc[mt][p*2+q], am, &bl[p][q*2]);
                    mma16816(acc[mt][p*2+q], av, &bh[p][q*2]);
                }
        }
        __syncthreads();
    }

    float* Cp = g_Spart + ((size_t)ks * G + g) * (C * C);
    int r0 = bx * 128 + warp_m * 64 + (lane >> 2);
    int c0 = by * 128 + warp_n * 32 + (lane & 3) * 2;
#pragma unroll
    for (int mt = 0; mt < 4; mt++)
#pragma unroll
        for (int nt = 0; nt < 4; nt++) {
            float* p = Cp + (size_t)(r0 + mt * 16) * C + c0 + nt * 8;
            *(float2*)p = make_float2(acc[mt][nt][0], acc[mt][nt][1]);
            *(float2*)(p + 8 * C) = make_float2(acc[mt][nt][2], acc[mt][nt][3]);
        }
}

// -------------- reduce split-K partials (tile (1,0) via symmetry), subtract d*mean*mean^T
__global__ void k_reduceS() {
    int idx = blockIdx.x * 256 + threadIdx.x;
    int g = idx >> 16, ij = idx & 65535;
    int i = ij >> 8, j = ij & 255;
    int src = (i >= 128 && j < 128) ? (j * C + i) : ij;
    float s = 0.f;
#pragma unroll
    for (int p = 0; p < SK; p++) s += g_Spart[((size_t)p * G + g) * (C * C) + src];
    s -= (float)D * g_mean[g * C + i] * g_mean[g * C + j];
    g_S[idx] = s;
}

// --------------------------- inf-norm per group (coalesced via symmetry)
__global__ void k_infnorm() {
    int g = blockIdx.x, x = threadIdx.x;
    const float* Sg = g_S + (size_t)g * (C * C);
    float s = 0.f;
    for (int i = 0; i < C; i++) s += fabsf(Sg[i * C + x]);
    __shared__ float red[256];
    red[x] = s;
    __syncthreads();
    for (int st = 128; st > 0; st >>= 1) {
        if (x < st) red[x] = fmaxf(red[x], red[x + st]);
        __syncthreads();
    }
    if (x == 0) g_norm[g] = red[0];
}

__global__ void k_initYZ(int ys, int zs) {
    int idx = blockIdx.x * 256 + threadIdx.x;
    int g = idx >> 16, ij = idx & 65535;
    float inv = 1.f / g_norm[g];
    g_ns[(size_t)ys * GV + idx] = g_S[idx] * inv;
    g_ns[(size_t)zs * GV + idx] = ((ij >> 8) == (ij & 255)) ? 1.f : 0.f;
}

// ----------------- batched 256x256x256 FFMA GEMM body (NS iterations)
__device__ __forceinline__ void gemm256_body(const float* __restrict__ A,
                                             const float* __restrict__ B,
                                             float* __restrict__ Cm, int mode,
                                             int bxx, int byy) {
    __shared__ float As[16][68];
    __shared__ float Bs[16][68];
    int tid = threadIdx.x;
    int arow = tid >> 2, ak4 = (tid & 3) * 4;
    int brow = tid >> 4, bcol4 = (tid & 15) * 4;
    int ty = tid >> 4, tx = tid & 15;

    float acc[4][4] = {};
    const float* Ap = A + (size_t)(bxx * 64 + arow) * C + ak4;
    const float* Bp = B + byy * 64 + bcol4;

    for (int k0 = 0; k0 < C; k0 += 16) {
        float4 av = *(const float4*)(Ap + k0);
        float4 bv = *(const float4*)(Bp + (size_t)(k0 + brow) * C);
        __syncthreads();
        As[ak4 + 0][arow] = av.x; As[ak4 + 1][arow] = av.y;
        As[ak4 + 2][arow] = av.z; As[ak4 + 3][arow] = av.w;
        *(float4*)&Bs[brow][bcol4] = bv;
        __syncthreads();
#pragma unroll
        for (int kk = 0; kk < 16; kk++) {
            float a[4], b[4];
            *(float4*)a = *(const float4*)&As[kk][ty * 4];
            *(float4*)b = *(const float4*)&Bs[kk][tx * 4];
#pragma unroll
            for (int i = 0; i < 4; i++)
#pragma unroll
                for (int j = 0; j < 4; j++) acc[i][j] = fmaf(a[i], b[j], acc[i][j]);
        }
    }
#pragma unroll
    for (int i = 0; i < 4; i++) {
        int r = bxx * 64 + ty * 4 + i;
#pragma unroll
        for (int j = 0; j < 4; j++) {
            int cc = byy * 64 + tx * 4 + j;
            float v = acc[i][j];
            if (mode == 1) v = ((r == cc) ? 1.5f : 0.f) - 0.5f * v;
            Cm[(size_t)r * C + cc] = v;
        }
    }
}

// T = 1.5 I - 0.5 (Z @ Y), grid (4,4,16)
__global__ void __launch_bounds__(256) k_gemmT(int zs, int ys, int ts) {
    const float* A = g_ns + (size_t)zs * GV + (size_t)blockIdx.z * (C * C);
    const float* B = g_ns + (size_t)ys * GV + (size_t)blockIdx.z * (C * C);
    float* Cm = g_ns + (size_t)ts * GV + (size_t)blockIdx.z * (C * C);
    gemm256_body(A, B, Cm, 1, blockIdx.x, blockIdx.y);
}
// Y' = Y@T (z<16) and Z' = T@Z (z>=16), grid (4,4,32)
__global__ void __launch_bounds__(256) k_gemmPair(int ys, int ts, int zs, int yn, int zn) {
    int zz = blockIdx.z;
    int grp = (zz < G) ? zz : zz - G;
    const float* A; const float* B; float* Cm;
    if (zz < G) {
        A = g_ns + (size_t)ys * GV + (size_t)grp * (C * C);
        B = g_ns + (size_t)ts * GV + (size_t)grp * (C * C);
        Cm = g_ns + (size_t)yn * GV + (size_t)grp * (C * C);
    } else {
        A = g_ns + (size_t)ts * GV + (size_t)grp * (C * C);
        B = g_ns + (size_t)zs * GV + (size_t)grp * (C * C);
        Cm = g_ns + (size_t)zn * GV + (size_t)grp * (C * C);
    }
    gemm256_body(A, B, Cm, 0, blockIdx.x, blockIdx.y);
}

// ---------------------------- corr = (Z_f/sqrt(s)) @ mean (warp per row)
__global__ void k_corr(int zs) {
    int g = blockIdx.x;
    int wid = threadIdx.x >> 5, lane = threadIdx.x & 31;
    const float* Z = g_ns + (size_t)zs * GV + (size_t)g * (C * C);
    const float* m = g_mean + g * C;
    float scale = rsqrtf(g_norm[g]);
    for (int r = wid; r < C; r += 8) {
        float s = 0.f;
        for (int j = lane; j < C; j += 32) s = fmaf(Z[(size_t)r * C + j], m[j], s);
#pragma unroll
        for (int o = 16; o > 0; o >>= 1) s += __shfl_xor_sync(0xFFFFFFFF, s, o);
        if (lane == 0) g_corr[g * C + r] = s * scale;
    }
}

// ------------------------------------------- split Z_f -> bf16 hi/lo
__global__ void k_zsplit(int zs) {
    int idx = blockIdx.x * 256 + threadIdx.x;
    float v = g_ns[(size_t)zs * GV + idx];
    __nv_bfloat16 h = __float2bfloat16_rn(v);
    g_Zhi[idx] = h;
    g_Zlo[idx] = __float2bfloat16_rn(v - __bfloat162float(h));
}

// ---------------------------------------------- mma.sync final GEMM
// out[g*C+i][d] = scale * sum_j Zf[i][j] W[j][d] - corr[i].  grid (2, 128, 16).
__global__ void __launch_bounds__(256) k_final_mma(const float* __restrict__ W,
                                                   float* __restrict__ out) {
    __shared__ char smbuf[2 * STAGE_F];    // 41984
    uint32_t sb = smem_u32(smbuf);
    int tid = threadIdx.x, lane = tid & 31, wid = tid >> 5;
    int warp_m = wid >> 2, warp_n = wid & 3;
    int g = blockIdx.z;
    int d0 = blockIdx.y * 128;

    const __nv_bfloat16* Ah = g_Zhi + (size_t)g * (C * C) + (size_t)blockIdx.x * 128 * C;
    const __nv_bfloat16* Al = g_Zlo + (size_t)g * (C * C) + (size_t)blockIdx.x * 128 * C;

    // A cp.async role
    int lrow = tid >> 1, half = tid & 1;
    uint32_t soA = (uint32_t)(lrow * LROW + half * 16);
    size_t goA = (size_t)lrow * C + half * 8;
    // B load/convert role: 16 j-rows x 128 d-cols f32
    int jrow = tid >> 4, c8 = (tid & 15) * 8;
    const float* pB = W + (size_t)(g * C + jrow) * D + d0 + c8;
    uint32_t soB = (uint32_t)(jrow * BROW + c8 * 2);

    uint32_t a_off = (warp_m * 64 + (lane & 15)) * LROW + (lane >> 4) * 16;
    uint32_t bt_off = (lane & 15) * BROW + ((warp_n * 32 + ((lane >> 4) << 3)) * 2);

    float acc[4][4][4] = {};

    auto issueA = [&](int s) {
        uint32_t st = sb + (s & 1) * STAGE_F;
        CP16(st + soA,        Ah + goA + (size_t)s * BK);
        CP16(st + MATA + soA, Al + goA + (size_t)s * BK);
        CP_COMMIT();
    };
    issueA(0);
    float4 b0 = *(const float4*)pB, b1 = *(const float4*)(pB + 4);

    const int NST = C / BK;   // 16
    for (int s = 0; s < NST; s++) {
        uint32_t st = sb + (s & 1) * STAGE_F;
        char* stp = smbuf + (s & 1) * STAGE_F;
        uint4 bh_, bl_;
        split8(b0, b1, bh_, bl_);
        *(uint4*)(stp + FB_HI + soB) = bh_;
        *(uint4*)(stp + FB_LO + soB) = bl_;
        if (s + 1 < NST) {
            issueA(s + 1);
            const float* q = pB + (size_t)(s + 1) * BK * D;
            b0 = *(const float4*)q; b1 = *(const float4*)(q + 4);
            CP_WAIT1();
        } else CP_WAIT0();
        __syncthreads();

        uint32_t bh[2][4], bl[2][4];
#pragma unroll
        for (int p = 0; p < 2; p++) {
            ldsm4t(bh[p], st + FB_HI + bt_off + p * 32);   // +16 cols = +32 bytes
            ldsm4t(bl[p], st + FB_LO + bt_off + p * 32);
        }
#pragma unroll
        for (int mt = 0; mt < 4; mt++) {
            uint32_t am[4], av[4];
            ldsm4(am, st + a_off + mt * 16 * LROW);
            ldsm4(av, st + MATA + a_off + mt * 16 * LROW);
#pragma unroll
            for (int p = 0; p < 2; p++)
#pragma unroll
                for (int q = 0; q < 2; q++) {
                    mma16816(acc[mt][p*2+q], am, &bh[p][q*2]);
                    mma16816(acc[mt][p*2+q], am, &bl[p][q*2]);
                    mma16816(acc[mt][p*2+q], av, &bh[p][q*2]);
                }
        }
        __syncthreads();
    }

    float scale = rsqrtf(g_norm[g]);
    int r0 = blockIdx.x * 128 + warp_m * 64 + (lane >> 2);
    int c0 = d0 + warp_n * 32 + (lane & 3) * 2;
#pragma unroll
    for (int mt = 0; mt < 4; mt++) {
        int r = r0 + mt * 16;
        float cr1 = g_corr[g * C + r];
        float cr2 = g_corr[g * C + r + 8];
        float* p1 = out + (size_t)(g * C + r) * D + c0;
        float* p2 = out + (size_t)(g * C + r + 8) * D + c0;
#pragma unroll
        for (int nt = 0; nt < 4; nt++) {
            *(float2*)(p1 + nt * 8) = make_float2(fmaf(scale, acc[mt][nt][0], -cr1),
                                                  fmaf(scale, acc[mt][nt][1], -cr1));
            *(float2*)(p2 + nt * 8) = make_float2(fmaf(scale, acc[mt][nt][2], -cr2),
                                                  fmaf(scale, acc[mt][nt][3], -cr2));
        }
    }
}

extern "C" void kernel_launch(void* const* d_in, const int* in_sizes, int n_in,
                              void* d_out, int out_size) {
    const float* W = (const float*)d_in[0];
    float* out = (float*)d_out;

    k_mean<<<NROW, 256>>>(W);
    k_syrk_mma<<<dim3(3, 1, G * SK), 256>>>(W);
    k_reduceS<<<GV / 256, 256>>>();
    k_infnorm<<<G, 256>>>();

    int y = 0, z = 1, ya = 2, za = 3, T = 4;
    k_initYZ<<<GV / 256, 256>>>(y, z);
    for (int it = 0; it < NS_ITERS; it++) {
        k_gemmT<<<dim3(4, 4, G), 256>>>(z, y, T);
        k_gemmPair<<<dim3(4, 4, 2 * G), 256>>>(y, T, z, ya, za);
        int t1 = y; y = ya; ya = t1;
        t1 = z; z = za; za = t1;
    }
    k_corr<<<G, 256>>>(z);
    k_zsplit<<<GV / 256, 256>>>(z);
    k_final_mma<<<dim3(2, D / 128, G), 256>>>(W, out);
}